// round 1
// baseline (speedup 1.0000x reference)
#include <cuda_runtime.h>
#include <cuda_bf16.h>
#include <cstdint>

// Problem constants
#define BS_ROWS 4096      // B*S
#define NHEAD   8
#define DIM     64        // d == D_head
#define NLAND   2048      // landmarks per head
#define DOUT    512
#define ALPHA_C 0.5f
#define BETA_C  0.5f
#define EPS_C   1e-12f

// Scratch (device globals: no allocation allowed)
__device__ float g_R2[NHEAD * NLAND];
__device__ float g_qa[NHEAD * NLAND];
__device__ float g_y [BS_ROWS * DOUT];   // 8 MB intermediate y = concat_h y_h

// ---------------------------------------------------------------------------
// Kernel 0: precompute per-landmark ||R||^2 and qpos^(-alpha)
// ---------------------------------------------------------------------------
__global__ void prep_kernel(const float* __restrict__ R, const float* __restrict__ q)
{
    int idx = blockIdx.x * blockDim.x + threadIdx.x;   // h*NLAND + n
    if (idx < NHEAD * NLAND) {
        const float* r = R + (size_t)idx * DIM;
        float s = 0.f;
        #pragma unroll 16
        for (int k = 0; k < DIM; k++) s += r[k] * r[k];
        g_R2[idx] = s;
        float qq = q[idx];
        qq = (qq > 0.f ? qq : 0.f) + EPS_C;
        g_qa[idx] = rsqrtf(qq);                        // qpos^(-0.5)
    }
}

// ---------------------------------------------------------------------------
// Kernel 1: fused  K -> normalize -> P@W  per (head, 64-row tile)
//   block: 256 threads (16x16), BM=64 rows, BN=64 landmarks per tile
//   smem: sZt [64][68] (z transposed, [k][i])
//         sRt [64][68] (R tile transposed, [k][j]) -- ALIASED with sKt [j][i]
//   GEMM2 reads W straight from gmem (L1/L2 resident, 16 KB/tile)
// ---------------------------------------------------------------------------
#define BM 64
#define BN 64
#define LDA 68   // padded stride (floats): conflict-free float4 reads, 4-way stores

__global__ void __launch_bounds__(256)
fused_kernel(const float* __restrict__ z, const float* __restrict__ R,
             const float* __restrict__ W)
{
    __shared__ float sZt[DIM * LDA];      // [k][i]
    __shared__ float sRt[BN * LDA];       // [k][j], aliased as sKt[j][i]
    __shared__ float sZ2[BM];
    __shared__ float sR2[BN];
    __shared__ float sQa[BN];
    __shared__ float sScale[BM];

    float* sKt = sRt;                      // alias (sequenced by syncthreads)

    const int h    = blockIdx.y;
    const int row0 = blockIdx.x * BM;
    const int tid  = threadIdx.x;
    const int tx   = tid & 15;             // 0..15 -> landmark/dh quad
    const int ty   = tid >> 4;             // 0..15 -> row quad

    // ---- load z tile transposed: sZt[k][i] = z[row0+i, h, k] ----
    for (int t = tid; t < BM * DIM; t += 256) {
        int i = t >> 6, k = t & 63;
        sZt[k * LDA + i] = z[((size_t)(row0 + i) * NHEAD + h) * DIM + k];
    }
    __syncthreads();

    // ---- per-row squared norms ----
    if (tid < BM) {
        float s = 0.f;
        #pragma unroll 8
        for (int k = 0; k < DIM; k++) { float v = sZt[k * LDA + tid]; s += v * v; }
        sZ2[tid] = s;
    }

    float acc[4][4];                       // y accumulator: rows 4ty.., dh 4tx..
    float p1[4], p2[4];                    // per-row sum K, sum Kt (partial)
    #pragma unroll
    for (int r = 0; r < 4; r++) {
        p1[r] = 0.f; p2[r] = 0.f;
        #pragma unroll
        for (int c = 0; c < 4; c++) acc[r][c] = 0.f;
    }

    const float* Rh  = R + (size_t)h * NLAND * DIM;
    const float* Wh  = W + (size_t)h * NLAND * DIM;
    const float* R2h = g_R2 + h * NLAND;
    const float* Qah = g_qa + h * NLAND;

    for (int n0 = 0; n0 < NLAND; n0 += BN) {
        __syncthreads();   // previous tile's sKt readers done before overwriting sRt

        // ---- load R tile transposed: sRt[k][j] = R[h, n0+j, k] ----
        for (int t = tid; t < BN * DIM; t += 256) {
            int j = t >> 6, k = t & 63;
            sRt[k * LDA + j] = Rh[(size_t)(n0 + j) * DIM + k];
        }
        if (tid < BN) { sR2[tid] = R2h[n0 + tid]; sQa[tid] = Qah[n0 + tid]; }
        __syncthreads();

        // ---- GEMM1: S[i][j] = sum_k z[i][k] * R[j][k] ----
        float S[4][4];
        #pragma unroll
        for (int r = 0; r < 4; r++)
            #pragma unroll
            for (int c = 0; c < 4; c++) S[r][c] = 0.f;

        #pragma unroll 8
        for (int k = 0; k < DIM; k++) {
            float4 a = *reinterpret_cast<const float4*>(&sZt[k * LDA + 4 * ty]);
            float4 b = *reinterpret_cast<const float4*>(&sRt[k * LDA + 4 * tx]);
            float av[4] = {a.x, a.y, a.z, a.w};
            float bv[4] = {b.x, b.y, b.z, b.w};
            #pragma unroll
            for (int r = 0; r < 4; r++)
                #pragma unroll
                for (int c = 0; c < 4; c++) S[r][c] += av[r] * bv[c];
        }

        // ---- elementwise: dist2 -> K -> Kt; accumulate row sums ----
        float z2v[4], r2v[4], qav[4];
        #pragma unroll
        for (int r = 0; r < 4; r++) z2v[r] = sZ2[4 * ty + r];
        #pragma unroll
        for (int c = 0; c < 4; c++) { r2v[c] = sR2[4 * tx + c]; qav[c] = sQa[4 * tx + c]; }

        float Kt[4][4];
        #pragma unroll
        for (int r = 0; r < 4; r++) {
            #pragma unroll
            for (int c = 0; c < 4; c++) {
                float d2 = z2v[r] - 2.f * S[r][c] + r2v[c];
                d2 = fmaxf(d2, 0.f);
                float K = __expf(-BETA_C * d2);
                p1[r] += K;
                float kt = K * qav[c];
                p2[r] += kt;
                Kt[r][c] = kt;
            }
        }

        __syncthreads();   // all GEMM1 reads of sRt complete

        // ---- store Kt transposed into aliased buffer: sKt[j][i] ----
        #pragma unroll
        for (int c = 0; c < 4; c++) {
            float4 v = make_float4(Kt[0][c], Kt[1][c], Kt[2][c], Kt[3][c]);
            *reinterpret_cast<float4*>(&sKt[(4 * tx + c) * LDA + 4 * ty]) = v;
        }
        __syncthreads();

        // ---- GEMM2: acc[i][dh] += sum_j Kt[i][j] * W[n0+j][dh] ----
        // W read directly from gmem (16 KB/tile, L1/L2 resident)
        #pragma unroll 4
        for (int j = 0; j < BN; j++) {
            float4 a = *reinterpret_cast<const float4*>(&sKt[j * LDA + 4 * ty]);
            float4 b = *reinterpret_cast<const float4*>(&Wh[(size_t)(n0 + j) * DIM + 4 * tx]);
            float av[4] = {a.x, a.y, a.z, a.w};
            float bv[4] = {b.x, b.y, b.z, b.w};
            #pragma unroll
            for (int r = 0; r < 4; r++)
                #pragma unroll
                for (int c = 0; c < 4; c++) acc[r][c] += av[r] * bv[c];
        }
    }

    // ---- reduce p1,p2 across the 16 tx lanes (within half-warps) ----
    #pragma unroll
    for (int r = 0; r < 4; r++) {
        float v1 = p1[r], v2 = p2[r];
        #pragma unroll
        for (int m = 8; m >= 1; m >>= 1) {
            v1 += __shfl_xor_sync(0xffffffffu, v1, m);
            v2 += __shfl_xor_sync(0xffffffffu, v2, m);
        }
        p1[r] = v1; p2[r] = v2;
    }
    if (tx == 0) {
        #pragma unroll
        for (int r = 0; r < 4; r++) {
            float S1 = fmaxf(p1[r], EPS_C);          // Ksum clamp
            float c  = rsqrtf(S1);                   // Ksum^(-alpha)
            float rs = fmaxf(c * p2[r], EPS_C);      // row_sum clamp
            sScale[4 * ty + r] = c / rs;
        }
    }
    __syncthreads();

    // ---- scaled writeback: y[row, h*64 + dh] ----
    #pragma unroll
    for (int r = 0; r < 4; r++) {
        float sc = sScale[4 * ty + r];
        float4 o = make_float4(acc[r][0] * sc, acc[r][1] * sc,
                               acc[r][2] * sc, acc[r][3] * sc);
        *reinterpret_cast<float4*>(
            &g_y[(size_t)(row0 + 4 * ty + r) * DOUT + h * DIM + 4 * tx]) = o;
    }
}

// ---------------------------------------------------------------------------
// Kernel 2: out = y @ W_O + b_O     (4096 x 512) @ (512 x 512)
// ---------------------------------------------------------------------------
#define BK2 64

__global__ void __launch_bounds__(256)
out_gemm_kernel(const float* __restrict__ WO, const float* __restrict__ bO,
                float* __restrict__ out)
{
    __shared__ float sYt[BK2 * LDA];   // y tile transposed [k][i]
    __shared__ float sB [BK2 * LDA];   // W_O tile [k][j]

    const int row0 = blockIdx.x * 64;
    const int col0 = blockIdx.y * 64;
    const int tid  = threadIdx.x;
    const int tx   = tid & 15;
    const int ty   = tid >> 4;

    float acc[4][4];
    #pragma unroll
    for (int r = 0; r < 4; r++)
        #pragma unroll
        for (int c = 0; c < 4; c++) acc[r][c] = 0.f;

    for (int k0 = 0; k0 < DOUT; k0 += BK2) {
        __syncthreads();
        for (int t = tid; t < 64 * BK2; t += 256) {
            int i = t >> 6, k = t & 63;
            sYt[k * LDA + i] = g_y[(size_t)(row0 + i) * DOUT + k0 + k];
        }
        for (int t = tid; t < BK2 * 64; t += 256) {
            int k = t >> 6, j = t & 63;
            sB[k * LDA + j] = WO[(size_t)(k0 + k) * DOUT + col0 + j];
        }
        __syncthreads();

        #pragma unroll 8
        for (int k = 0; k < BK2; k++) {
            float4 a = *reinterpret_cast<const float4*>(&sYt[k * LDA + 4 * ty]);
            float4 b = *reinterpret_cast<const float4*>(&sB [k * LDA + 4 * tx]);
            float av[4] = {a.x, a.y, a.z, a.w};
            float bv[4] = {b.x, b.y, b.z, b.w};
            #pragma unroll
            for (int r = 0; r < 4; r++)
                #pragma unroll
                for (int c = 0; c < 4; c++) acc[r][c] += av[r] * bv[c];
        }
    }

    #pragma unroll
    for (int r = 0; r < 4; r++) {
        int row = row0 + 4 * ty + r;
        #pragma unroll
        for (int c = 0; c < 4; c++) {
            int col = col0 + 4 * tx + c;
            out[(size_t)row * DOUT + col] = acc[r][c] + bO[col];
        }
    }
}

// ---------------------------------------------------------------------------
extern "C" void kernel_launch(void* const* d_in, const int* in_sizes, int n_in,
                              void* d_out, int out_size)
{
    const float* z  = (const float*)d_in[0];   // (4,1024,8,64)
    const float* R  = (const float*)d_in[1];   // (8,2048,64)
    const float* q  = (const float*)d_in[2];   // (8,2048)
    const float* W  = (const float*)d_in[3];   // (8,2048,64)
    const float* WO = (const float*)d_in[4];   // (512,512)
    const float* bO = (const float*)d_in[5];   // (512)
    float* out = (float*)d_out;                // (4,1024,512)
    (void)in_sizes; (void)n_in; (void)out_size;

    prep_kernel<<<(NHEAD * NLAND + 255) / 256, 256>>>(R, q);

    dim3 gridF(BS_ROWS / BM, NHEAD);           // (64, 8)
    fused_kernel<<<gridF, 256>>>(z, R, W);

    dim3 gridO(BS_ROWS / 64, DOUT / 64);       // (64, 8)
    out_gemm_kernel<<<gridO, 256>>>(WO, bO, out);
}